// round 1
// baseline (speedup 1.0000x reference)
#include <cuda_runtime.h>
#include <cstdint>
#include <cstddef>

#define N_TOK 4096
#define HDIM  1024
#define NE    8
#define CAP   1536
#define HCOLS 2560   // 512 (imp hidden) + 1024 (router imp) + 1024 (router unimp)

// ---------------- scratch (static device globals: no allocation) ----------------
__device__ float g_h[(size_t)N_TOK * HCOLS];   // fused hidden activations
__device__ float g_p0[N_TOK], g_p1[N_TOK];     // normalized top-2 gate probs
__device__ int   g_e0[N_TOK], g_e1[N_TOK];     // top-2 expert ids
__device__ unsigned char g_mask[N_TOK];        // importance mask

// ---------------- packed f32x2 helpers ----------------
static __device__ __forceinline__ void fma2(unsigned long long& d,
                                            unsigned long long a,
                                            unsigned long long b) {
    asm("fma.rn.f32x2 %0, %1, %2, %0;" : "+l"(d) : "l"(a), "l"(b));
}
static __device__ __forceinline__ unsigned long long pack2(float x, float y) {
    unsigned long long r;
    asm("mov.b64 %0, {%1, %2};" : "=l"(r) : "f"(x), "f"(y));
    return r;
}
static __device__ __forceinline__ float2 unpack2(unsigned long long v) {
    float2 r;
    asm("mov.b64 {%0, %1}, %2;" : "=f"(r.x), "=f"(r.y) : "l"(v));
    return r;
}

// ---------------- Kernel 1: fused fp32 SGEMM (relu(X@W + b)) for all 3 weight mats ---
// C[4096, 2560] tiled 128x128, BK=8, 256 threads, 8x8 microtile via fma.rn.f32x2.
__global__ __launch_bounds__(256, 2)
void gemm_kernel(const float* __restrict__ x,
                 const float* __restrict__ wi1, const float* __restrict__ bi1,
                 const float* __restrict__ wr1, const float* __restrict__ br1,
                 const float* __restrict__ wu1, const float* __restrict__ bu1) {
    __shared__ __align__(16) float As[2][8][128];
    __shared__ __align__(16) float Bs[2][8][128];

    const int nt = blockIdx.x;          // 20 column tiles total
    const float* W; const float* bias; int ldw, ncol0, cb;
    if (nt < 4)       { W = wi1; bias = bi1; ldw = 512;  ncol0 = nt * 128;        cb = 0;    }
    else if (nt < 12) { W = wr1; bias = br1; ldw = 1024; ncol0 = (nt - 4) * 128;  cb = 512;  }
    else              { W = wu1; bias = bu1; ldw = 1024; ncol0 = (nt - 12) * 128; cb = 1536; }

    const int m0  = blockIdx.y * 128;
    const int tid = threadIdx.x;
    const int arow = tid >> 1,  acol = (tid & 1) * 4;
    const int brow = tid >> 5,  bcol = (tid & 31) * 4;
    const float* Ap = x + (size_t)(m0 + arow) * HDIM + acol;
    const float* Bp = W + (size_t)brow * ldw + ncol0 + bcol;
    const int trow = (tid >> 4) * 8;
    const int tcol = (tid & 15) * 8;

    // preload tile 0
    float4 a_ld = *(const float4*)Ap;
    float4 b_ld = *(const float4*)Bp;
    As[0][acol + 0][arow] = a_ld.x;
    As[0][acol + 1][arow] = a_ld.y;
    As[0][acol + 2][arow] = a_ld.z;
    As[0][acol + 3][arow] = a_ld.w;
    *(float4*)&Bs[0][brow][bcol] = b_ld;
    __syncthreads();

    unsigned long long acc[8][4];
#pragma unroll
    for (int i = 0; i < 8; i++)
#pragma unroll
        for (int j = 0; j < 4; j++) acc[i][j] = 0ull;

    for (int kt = 0; kt < 128; kt++) {
        const int cur = kt & 1;
        float4 a_n, b_n;
        if (kt < 127) {
            a_n = *(const float4*)(Ap + (kt + 1) * 8);
            b_n = *(const float4*)(Bp + (size_t)(kt + 1) * 8 * ldw);
        }
#pragma unroll
        for (int k = 0; k < 8; k++) {
            float4 a0 = *(const float4*)&As[cur][k][trow];
            float4 a1 = *(const float4*)&As[cur][k][trow + 4];
            ulonglong2 bq0 = *(const ulonglong2*)&Bs[cur][k][tcol];
            ulonglong2 bq1 = *(const ulonglong2*)&Bs[cur][k][tcol + 4];
            const unsigned long long bb0 = bq0.x, bb1 = bq0.y, bb2 = bq1.x, bb3 = bq1.y;
            float av[8] = {a0.x, a0.y, a0.z, a0.w, a1.x, a1.y, a1.z, a1.w};
#pragma unroll
            for (int i = 0; i < 8; i++) {
                unsigned long long aa = pack2(av[i], av[i]);
                fma2(acc[i][0], aa, bb0);
                fma2(acc[i][1], aa, bb1);
                fma2(acc[i][2], aa, bb2);
                fma2(acc[i][3], aa, bb3);
            }
        }
        if (kt < 127) {
            const int nxt = cur ^ 1;
            As[nxt][acol + 0][arow] = a_n.x;
            As[nxt][acol + 1][arow] = a_n.y;
            As[nxt][acol + 2][arow] = a_n.z;
            As[nxt][acol + 3][arow] = a_n.w;
            *(float4*)&Bs[nxt][brow][bcol] = b_n;
            __syncthreads();
        }
    }

    // epilogue: +bias, relu, store to fused hidden buffer
    const int gcol = cb + ncol0 + tcol;
#pragma unroll
    for (int i = 0; i < 8; i++) {
        float* hr = g_h + (size_t)(m0 + trow + i) * HCOLS + gcol;
#pragma unroll
        for (int j = 0; j < 4; j++) {
            float2 v = unpack2(acc[i][j]);
            v.x = fmaxf(v.x + bias[ncol0 + tcol + 2 * j],     0.0f);
            v.y = fmaxf(v.y + bias[ncol0 + tcol + 2 * j + 1], 0.0f);
            *(float2*)(hr + 2 * j) = v;
        }
    }
}

// ---------------- Kernel 2: per-token second layers + gate + softmax + top-2 -------
__global__ void routing_kernel(const float* __restrict__ wi2, const float* __restrict__ bi2,
                               const float* __restrict__ wr2, const float* __restrict__ br2,
                               const float* __restrict__ wu2, const float* __restrict__ bu2,
                               float* __restrict__ out_probs, float* __restrict__ out_imp) {
    const int gt   = (blockIdx.x * blockDim.x + threadIdx.x) >> 5;   // token (warp) id
    const int lane = threadIdx.x & 31;
    if (gt >= N_TOK) return;
    const float* hr = g_h + (size_t)gt * HCOLS;

    // importance score z = h_imp @ wi2 + bi2
    float z = 0.0f;
    for (int j = lane; j < 512; j += 32) z = fmaf(hr[j], wi2[j], z);
#pragma unroll
    for (int off = 16; off > 0; off >>= 1) z += __shfl_xor_sync(0xffffffffu, z, off);
    z += bi2[0];
    const float sig = 1.0f / (1.0f + expf(-z));
    const bool m = sig > 0.5f;

    // selected router logits (only the gated branch is needed)
    const float* hs = hr + (m ? 512 : 1536);
    const float* W2 = m ? wr2 : wu2;
    const float* b2 = m ? br2 : bu2;
    float acc[NE];
#pragma unroll
    for (int e = 0; e < NE; e++) acc[e] = 0.0f;
    for (int j = lane; j < 1024; j += 32) {
        const float hv = hs[j];
        float4 w0 = *(const float4*)(W2 + (size_t)j * 8);
        float4 w1 = *(const float4*)(W2 + (size_t)j * 8 + 4);
        acc[0] = fmaf(hv, w0.x, acc[0]);
        acc[1] = fmaf(hv, w0.y, acc[1]);
        acc[2] = fmaf(hv, w0.z, acc[2]);
        acc[3] = fmaf(hv, w0.w, acc[3]);
        acc[4] = fmaf(hv, w1.x, acc[4]);
        acc[5] = fmaf(hv, w1.y, acc[5]);
        acc[6] = fmaf(hv, w1.z, acc[6]);
        acc[7] = fmaf(hv, w1.w, acc[7]);
    }
#pragma unroll
    for (int off = 16; off > 0; off >>= 1)
#pragma unroll
        for (int e = 0; e < NE; e++) acc[e] += __shfl_xor_sync(0xffffffffu, acc[e], off);

    if (lane == 0) {
        float l[NE], pr[NE];
        float mx = -1e30f;
#pragma unroll
        for (int e = 0; e < NE; e++) { l[e] = acc[e] + b2[e]; mx = fmaxf(mx, l[e]); }
        float s = 0.0f;
#pragma unroll
        for (int e = 0; e < NE; e++) { pr[e] = expf(l[e] - mx); s += pr[e]; }
        const float inv = 1.0f / s;
#pragma unroll
        for (int e = 0; e < NE; e++) { pr[e] *= inv; out_probs[(size_t)gt * NE + e] = pr[e]; }
        out_imp[gt] = sig;
        g_mask[gt] = m ? 1 : 0;

        // top-2, ties -> lower index (matches lax.top_k)
        int e0 = 0; float p0v = pr[0];
#pragma unroll
        for (int e = 1; e < NE; e++) if (pr[e] > p0v) { p0v = pr[e]; e0 = e; }
        int e1 = -1; float p1v = -1.0f;
#pragma unroll
        for (int e = 0; e < NE; e++) if (e != e0 && pr[e] > p1v) { p1v = pr[e]; e1 = e; }
        const float sn = p0v + p1v;
        g_e0[gt] = e0; g_e1[gt] = e1;
        g_p0[gt] = p0v / sn; g_p1[gt] = p1v / sn;
    }
}

// ---------------- Kernel 3: capacity-constrained dispatch (k-major running count) --
__global__ void dispatch_kernel(float* __restrict__ disp, float* __restrict__ comb) {
    __shared__ int base[NE];
    __shared__ int whist[32][NE];
    __shared__ int wpref[32][NE];
    const int tid  = threadIdx.x;
    const int lane = tid & 31, warp = tid >> 5;
    if (tid < NE) base[tid] = 0;
    __syncthreads();

    for (int chunk = 0; chunk < 8; chunk++) {     // 8192 entries, 1024 at a time, in order
        const int i = chunk * 1024 + tid;
        const int k = i >> 12;                    // i / 4096  (k-major)
        const int t = i & (N_TOK - 1);
        const int e   = (k == 0) ? g_e0[t] : g_e1[t];
        const float p = (k == 0) ? g_p0[t] : g_p1[t];

        if (lane < NE) whist[warp][lane] = 0;
        __syncwarp();
        const unsigned mm  = __match_any_sync(0xffffffffu, e);
        const unsigned blo = mm & ((1u << lane) - 1u);
        const int rank = __popc(blo);
        if (blo == 0u) whist[warp][e] = __popc(mm);   // lowest-lane leader writes count
        __syncthreads();

        if (tid < NE) {                            // serial exclusive scan over 32 warps
            int s = base[tid];
            for (int w = 0; w < 32; w++) { wpref[w][tid] = s; s += whist[w][tid]; }
            base[tid] = s;
        }
        __syncthreads();

        const int pos = wpref[warp][e] + rank;
        if (pos < CAP) {
            const size_t idx = ((size_t)t * NE + e) * CAP + pos;
            disp[idx] = 1.0f;
            comb[idx] = p;
        }
        __syncthreads();
    }
}

// ---------------- Kernel 4: aux loss (deterministic reduction) ---------------------
__global__ void aux_kernel(const float* __restrict__ probs, float* __restrict__ out_aux) {
    const int tid = threadIdx.x;
    float s[NE], si[NE];
#pragma unroll
    for (int e = 0; e < NE; e++) { s[e] = 0.0f; si[e] = 0.0f; }
    for (int t = tid; t < N_TOK; t += 256) {
        const float m = g_mask[t] ? 1.0f : 0.0f;
#pragma unroll
        for (int e = 0; e < NE; e++) {
            const float p = probs[(size_t)t * NE + e];
            s[e]  += p;
            si[e] += p * m;
        }
    }
#pragma unroll
    for (int off = 16; off > 0; off >>= 1)
#pragma unroll
        for (int e = 0; e < NE; e++) {
            s[e]  += __shfl_xor_sync(0xffffffffu, s[e],  off);
            si[e] += __shfl_xor_sync(0xffffffffu, si[e], off);
        }
    __shared__ float sm[8][2 * NE];
    const int warp = tid >> 5, lane = tid & 31;
    if (lane == 0) {
#pragma unroll
        for (int e = 0; e < NE; e++) { sm[warp][e] = s[e]; sm[warp][NE + e] = si[e]; }
    }
    __syncthreads();
    if (tid == 0) {
        float S[NE], SI[NE];
#pragma unroll
        for (int e = 0; e < NE; e++) { S[e] = 0.0f; SI[e] = 0.0f; }
        for (int w = 0; w < 8; w++)
#pragma unroll
            for (int e = 0; e < NE; e++) { S[e] += sm[w][e]; SI[e] += sm[w][NE + e]; }
        float ent = 0.0f;
#pragma unroll
        for (int e = 0; e < NE; e++) {
            const float r = S[e] / (float)N_TOK;
            ent += r * logf(r * 8.0f + 1e-9f);
        }
        float tot = 0.0f;
#pragma unroll
        for (int e = 0; e < NE; e++) { SI[e] += 1e-9f; tot += SI[e]; }
        float ie = 0.0f;
#pragma unroll
        for (int e = 0; e < NE; e++) {
            const float ip = SI[e] / tot;
            ie -= ip * logf(ip + 1e-9f);
        }
        out_aux[0] = ent - 0.1f * (ie / logf(8.0f));
    }
}

// ---------------- launch -----------------------------------------------------------
extern "C" void kernel_launch(void* const* d_in, const int* in_sizes, int n_in,
                              void* d_out, int out_size) {
    const float* x   = (const float*)d_in[0];
    const float* wi1 = (const float*)d_in[1];
    const float* bi1 = (const float*)d_in[2];
    const float* wi2 = (const float*)d_in[3];
    const float* bi2 = (const float*)d_in[4];
    const float* wr1 = (const float*)d_in[5];
    const float* br1 = (const float*)d_in[6];
    const float* wr2 = (const float*)d_in[7];
    const float* br2 = (const float*)d_in[8];
    const float* wu1 = (const float*)d_in[9];
    const float* bu1 = (const float*)d_in[10];
    const float* wu2 = (const float*)d_in[11];
    const float* bu2 = (const float*)d_in[12];

    float* out   = (float*)d_out;
    float* disp  = out;                                   // [4096, 8, 1536]
    float* comb  = disp + (size_t)N_TOK * NE * CAP;       // [4096, 8, 1536]
    float* probs = comb + (size_t)N_TOK * NE * CAP;       // [4096, 8]
    float* aux   = probs + (size_t)N_TOK * NE;            // [1]
    float* imp   = aux + 1;                               // [4096]

    // zero the sparse outputs (dispatch + combine); everything else fully written
    cudaMemsetAsync(disp, 0, (size_t)2 * N_TOK * NE * CAP * sizeof(float), 0);

    dim3 g(20, 32);
    gemm_kernel<<<g, 256>>>(x, wi1, bi1, wr1, br1, wu1, bu1);
    routing_kernel<<<512, 256>>>(wi2, bi2, wr2, br2, wu2, bu2, probs, imp);
    dispatch_kernel<<<1, 1024>>>(disp, comb);
    aux_kernel<<<1, 256>>>(probs, aux);
}

// round 2
// speedup vs baseline: 1.3943x; 1.3943x over previous
#include <cuda_runtime.h>
#include <cstdint>
#include <cstddef>

#define N_TOK 4096
#define HDIM  1024
#define NE    8
#define CAP   1536

// ---------------- scratch (static device globals: no allocation) ----------------
__device__ float g_hi[(size_t)N_TOK * 512];    // importance hidden
__device__ float g_hr[(size_t)N_TOK * 1024];   // selected-router hidden (per token)
__device__ float g_p0[N_TOK], g_p1[N_TOK];     // normalized top-2 gate probs
__device__ int   g_e0[N_TOK], g_e1[N_TOK];     // top-2 expert ids
__device__ unsigned char g_mask[N_TOK];        // importance mask
__device__ int   g_idx_i[N_TOK], g_idx_u[N_TOK];
__device__ int   g_cnt[2];
__device__ float g_part[512 * 16];             // aux partial sums per routing block

// ---------------- packed f32x2 helpers ----------------
static __device__ __forceinline__ void fma2(unsigned long long& d,
                                            unsigned long long a,
                                            unsigned long long b) {
    asm("fma.rn.f32x2 %0, %1, %2, %0;" : "+l"(d) : "l"(a), "l"(b));
}
static __device__ __forceinline__ unsigned long long pack2(float x, float y) {
    unsigned long long r;
    asm("mov.b64 %0, {%1, %2};" : "=l"(r) : "f"(x), "f"(y));
    return r;
}
static __device__ __forceinline__ float2 unpack2(unsigned long long v) {
    float2 r;
    asm("mov.b64 {%0, %1}, %2;" : "=f"(r.x), "=f"(r.y) : "l"(v));
    return r;
}

// ---------------- Phase A: importance first-layer GEMM  relu(X@wi1 + bi1) ----------
// C[4096, 512] tiled 128x128, BK=8, 256 threads, 8x8 microtile via fma.rn.f32x2.
__global__ __launch_bounds__(256, 2)
void gemmA_kernel(const float* __restrict__ x,
                  const float* __restrict__ wi1, const float* __restrict__ bi1) {
    __shared__ __align__(16) float As[2][8][128];
    __shared__ __align__(16) float Bs[2][8][128];

    const int ncol0 = blockIdx.x * 128;    // 4 col tiles
    const int m0    = blockIdx.y * 128;    // 32 row tiles
    const int tid   = threadIdx.x;
    const int arow = tid >> 1,  acol = (tid & 1) * 4;
    const int brow = tid >> 5,  bcol = (tid & 31) * 4;
    const float* Ap = x   + (size_t)(m0 + arow) * HDIM + acol;
    const float* Bp = wi1 + (size_t)brow * 512 + ncol0 + bcol;
    const int trow = (tid >> 4) * 8;
    const int tcol = (tid & 15) * 8;

    float4 a_ld = *(const float4*)Ap;
    float4 b_ld = *(const float4*)Bp;
    As[0][acol + 0][arow] = a_ld.x;
    As[0][acol + 1][arow] = a_ld.y;
    As[0][acol + 2][arow] = a_ld.z;
    As[0][acol + 3][arow] = a_ld.w;
    *(float4*)&Bs[0][brow][bcol] = b_ld;
    __syncthreads();

    unsigned long long acc[8][4];
#pragma unroll
    for (int i = 0; i < 8; i++)
#pragma unroll
        for (int j = 0; j < 4; j++) acc[i][j] = 0ull;

    for (int kt = 0; kt < 128; kt++) {
        const int cur = kt & 1;
        float4 a_n, b_n;
        if (kt < 127) {
            a_n = *(const float4*)(Ap + (kt + 1) * 8);
            b_n = *(const float4*)(Bp + (size_t)(kt + 1) * 8 * 512);
        }
#pragma unroll
        for (int k = 0; k < 8; k++) {
            float4 a0 = *(const float4*)&As[cur][k][trow];
            float4 a1 = *(const float4*)&As[cur][k][trow + 4];
            ulonglong2 bq0 = *(const ulonglong2*)&Bs[cur][k][tcol];
            ulonglong2 bq1 = *(const ulonglong2*)&Bs[cur][k][tcol + 4];
            const unsigned long long bb0 = bq0.x, bb1 = bq0.y, bb2 = bq1.x, bb3 = bq1.y;
            float av[8] = {a0.x, a0.y, a0.z, a0.w, a1.x, a1.y, a1.z, a1.w};
#pragma unroll
            for (int i = 0; i < 8; i++) {
                unsigned long long aa = pack2(av[i], av[i]);
                fma2(acc[i][0], aa, bb0);
                fma2(acc[i][1], aa, bb1);
                fma2(acc[i][2], aa, bb2);
                fma2(acc[i][3], aa, bb3);
            }
        }
        if (kt < 127) {
            const int nxt = cur ^ 1;
            As[nxt][acol + 0][arow] = a_n.x;
            As[nxt][acol + 1][arow] = a_n.y;
            As[nxt][acol + 2][arow] = a_n.z;
            As[nxt][acol + 3][arow] = a_n.w;
            *(float4*)&Bs[nxt][brow][bcol] = b_n;
            __syncthreads();
        }
    }

#pragma unroll
    for (int i = 0; i < 8; i++) {
        float* hr = g_hi + (size_t)(m0 + trow + i) * 512 + ncol0 + tcol;
#pragma unroll
        for (int j = 0; j < 4; j++) {
            float2 v = unpack2(acc[i][j]);
            v.x = fmaxf(v.x + bi1[ncol0 + tcol + 2 * j],     0.0f);
            v.y = fmaxf(v.y + bi1[ncol0 + tcol + 2 * j + 1], 0.0f);
            *(float2*)(hr + 2 * j) = v;
        }
    }
}

// ---------------- importance score + mask (warp per token) -------------------------
__global__ void importance_kernel(const float* __restrict__ wi2, const float* __restrict__ bi2,
                                  float* __restrict__ out_imp) {
    const int gt   = (blockIdx.x * blockDim.x + threadIdx.x) >> 5;
    const int lane = threadIdx.x & 31;
    if (gt >= N_TOK) return;
    const float* hr = g_hi + (size_t)gt * 512;
    float z = 0.0f;
    for (int j = lane; j < 512; j += 32) z = fmaf(hr[j], wi2[j], z);
#pragma unroll
    for (int off = 16; off > 0; off >>= 1) z += __shfl_xor_sync(0xffffffffu, z, off);
    if (lane == 0) {
        z += bi2[0];
        const float sig = 1.0f / (1.0f + expf(-z));
        out_imp[gt] = sig;
        g_mask[gt] = (sig > 0.5f) ? 1 : 0;
    }
}

// ---------------- compaction: ordered token lists per branch -----------------------
__global__ void compact_kernel() {
    __shared__ int wcnt_i[32], wcnt_u[32], wpre_i[32], wpre_u[32];
    __shared__ int base_i, base_u;
    const int tid = threadIdx.x, lane = tid & 31, warp = tid >> 5;
    if (tid == 0) { base_i = 0; base_u = 0; }
    __syncthreads();
    for (int c = 0; c < 4; c++) {
        const int t = c * 1024 + tid;
        const int m = g_mask[t];
        const unsigned bi = __ballot_sync(0xffffffffu, m);
        const unsigned lt = (1u << lane) - 1u;
        if (lane == 0) { wcnt_i[warp] = __popc(bi); wcnt_u[warp] = 32 - __popc(bi); }
        __syncthreads();
        if (tid == 0) {
            int si = base_i, su = base_u;
            for (int w = 0; w < 32; w++) {
                wpre_i[w] = si; si += wcnt_i[w];
                wpre_u[w] = su; su += wcnt_u[w];
            }
            base_i = si; base_u = su;
        }
        __syncthreads();
        if (m) g_idx_i[wpre_i[warp] + __popc(bi & lt)] = t;
        else   g_idx_u[wpre_u[warp] + __popc(~bi & lt)] = t;
        __syncthreads();
    }
    if (tid == 0) { g_cnt[0] = base_i; g_cnt[1] = base_u; }
}

// ---------------- Phase C: gathered router first-layer GEMM ------------------------
// Row tiles cover imp list then unimp list; each token computed with ITS router only.
__global__ __launch_bounds__(256, 2)
void gemmC_kernel(const float* __restrict__ x,
                  const float* __restrict__ wr1, const float* __restrict__ br1,
                  const float* __restrict__ wu1, const float* __restrict__ bu1) {
    const int ci = g_cnt[0], cu = g_cnt[1];
    const int ti = (ci + 127) >> 7;
    const int by = blockIdx.y;
    const float* W; const float* bias; const int* list; int base, cnt;
    if (by < ti)                        { W = wr1; bias = br1; list = g_idx_i; base = by << 7;        cnt = ci; }
    else if (by < ti + ((cu + 127) >> 7)){ W = wu1; bias = bu1; list = g_idx_u; base = (by - ti) << 7; cnt = cu; }
    else return;

    __shared__ __align__(16) float As[2][8][128];
    __shared__ __align__(16) float Bs[2][8][128];
    __shared__ int s_tok[128];

    const int ncol0 = blockIdx.x * 128;
    const int tid   = threadIdx.x;
    if (tid < 128) {
        const int r = base + tid;
        s_tok[tid] = (r < cnt) ? list[r] : -1;
    }
    __syncthreads();

    const int arow = tid >> 1,  acol = (tid & 1) * 4;
    const int brow = tid >> 5,  bcol = (tid & 31) * 4;
    const int tokA = s_tok[arow];
    const float* Ap = x + (size_t)(tokA < 0 ? 0 : tokA) * HDIM + acol;
    const float* Bp = W + (size_t)brow * 1024 + ncol0 + bcol;
    const int trow = (tid >> 4) * 8;
    const int tcol = (tid & 15) * 8;

    float4 a_ld = *(const float4*)Ap;
    float4 b_ld = *(const float4*)Bp;
    As[0][acol + 0][arow] = a_ld.x;
    As[0][acol + 1][arow] = a_ld.y;
    As[0][acol + 2][arow] = a_ld.z;
    As[0][acol + 3][arow] = a_ld.w;
    *(float4*)&Bs[0][brow][bcol] = b_ld;
    __syncthreads();

    unsigned long long acc[8][4];
#pragma unroll
    for (int i = 0; i < 8; i++)
#pragma unroll
        for (int j = 0; j < 4; j++) acc[i][j] = 0ull;

    for (int kt = 0; kt < 128; kt++) {
        const int cur = kt & 1;
        float4 a_n, b_n;
        if (kt < 127) {
            a_n = *(const float4*)(Ap + (kt + 1) * 8);
            b_n = *(const float4*)(Bp + (size_t)(kt + 1) * 8 * 1024);
        }
#pragma unroll
        for (int k = 0; k < 8; k++) {
            float4 a0 = *(const float4*)&As[cur][k][trow];
            float4 a1 = *(const float4*)&As[cur][k][trow + 4];
            ulonglong2 bq0 = *(const ulonglong2*)&Bs[cur][k][tcol];
            ulonglong2 bq1 = *(const ulonglong2*)&Bs[cur][k][tcol + 4];
            const unsigned long long bb0 = bq0.x, bb1 = bq0.y, bb2 = bq1.x, bb3 = bq1.y;
            float av[8] = {a0.x, a0.y, a0.z, a0.w, a1.x, a1.y, a1.z, a1.w};
#pragma unroll
            for (int i = 0; i < 8; i++) {
                unsigned long long aa = pack2(av[i], av[i]);
                fma2(acc[i][0], aa, bb0);
                fma2(acc[i][1], aa, bb1);
                fma2(acc[i][2], aa, bb2);
                fma2(acc[i][3], aa, bb3);
            }
        }
        if (kt < 127) {
            const int nxt = cur ^ 1;
            As[nxt][acol + 0][arow] = a_n.x;
            As[nxt][acol + 1][arow] = a_n.y;
            As[nxt][acol + 2][arow] = a_n.z;
            As[nxt][acol + 3][arow] = a_n.w;
            *(float4*)&Bs[nxt][brow][bcol] = b_n;
            __syncthreads();
        }
    }

#pragma unroll
    for (int i = 0; i < 8; i++) {
        const int tok = s_tok[trow + i];
        if (tok < 0) continue;
        float* hr = g_hr + (size_t)tok * 1024 + ncol0 + tcol;
#pragma unroll
        for (int j = 0; j < 4; j++) {
            float2 v = unpack2(acc[i][j]);
            v.x = fmaxf(v.x + bias[ncol0 + tcol + 2 * j],     0.0f);
            v.y = fmaxf(v.y + bias[ncol0 + tcol + 2 * j + 1], 0.0f);
            *(float2*)(hr + 2 * j) = v;
        }
    }
}

// ---------------- routing: second layer + softmax + top-2 + aux partials -----------
__global__ void routing_kernel(const float* __restrict__ wr2, const float* __restrict__ br2,
                               const float* __restrict__ wu2, const float* __restrict__ bu2,
                               float* __restrict__ out_probs) {
    __shared__ float s_aux[8][16];   // [warp][ pr(8), pr*mask(8) ]
    const int gt   = (blockIdx.x * blockDim.x + threadIdx.x) >> 5;
    const int lane = threadIdx.x & 31;
    const int warp = threadIdx.x >> 5;
    if (gt < N_TOK) {
        const bool m = g_mask[gt] != 0;
        const float* hs = g_hr + (size_t)gt * 1024;
        const float* W2 = m ? wr2 : wu2;
        const float* b2 = m ? br2 : bu2;
        float acc[NE];
#pragma unroll
        for (int e = 0; e < NE; e++) acc[e] = 0.0f;
        for (int j = lane; j < 1024; j += 32) {
            const float hv = hs[j];
            float4 w0 = *(const float4*)(W2 + (size_t)j * 8);
            float4 w1 = *(const float4*)(W2 + (size_t)j * 8 + 4);
            acc[0] = fmaf(hv, w0.x, acc[0]);
            acc[1] = fmaf(hv, w0.y, acc[1]);
            acc[2] = fmaf(hv, w0.z, acc[2]);
            acc[3] = fmaf(hv, w0.w, acc[3]);
            acc[4] = fmaf(hv, w1.x, acc[4]);
            acc[5] = fmaf(hv, w1.y, acc[5]);
            acc[6] = fmaf(hv, w1.z, acc[6]);
            acc[7] = fmaf(hv, w1.w, acc[7]);
        }
#pragma unroll
        for (int off = 16; off > 0; off >>= 1)
#pragma unroll
            for (int e = 0; e < NE; e++) acc[e] += __shfl_xor_sync(0xffffffffu, acc[e], off);

        if (lane == 0) {
            float l[NE], pr[NE];
            float mx = -1e30f;
#pragma unroll
            for (int e = 0; e < NE; e++) { l[e] = acc[e] + b2[e]; mx = fmaxf(mx, l[e]); }
            float s = 0.0f;
#pragma unroll
            for (int e = 0; e < NE; e++) { pr[e] = expf(l[e] - mx); s += pr[e]; }
            const float inv = 1.0f / s;
            const float mf = m ? 1.0f : 0.0f;
#pragma unroll
            for (int e = 0; e < NE; e++) {
                pr[e] *= inv;
                out_probs[(size_t)gt * NE + e] = pr[e];
                s_aux[warp][e]      = pr[e];
                s_aux[warp][NE + e] = pr[e] * mf;
            }
            // top-2, ties -> lower index (matches lax.top_k)
            int e0 = 0; float p0v = pr[0];
#pragma unroll
            for (int e = 1; e < NE; e++) if (pr[e] > p0v) { p0v = pr[e]; e0 = e; }
            int e1 = -1; float p1v = -1.0f;
#pragma unroll
            for (int e = 0; e < NE; e++) if (e != e0 && pr[e] > p1v) { p1v = pr[e]; e1 = e; }
            const float sn = p0v + p1v;
            g_e0[gt] = e0; g_e1[gt] = e1;
            g_p0[gt] = p0v / sn; g_p1[gt] = p1v / sn;
        }
    }
    __syncthreads();
    if (threadIdx.x < 16) {   // deterministic fixed-order partial sum over 8 warps
        float s = 0.0f;
        for (int w = 0; w < 8; w++) s += s_aux[w][threadIdx.x];
        g_part[(size_t)blockIdx.x * 16 + threadIdx.x] = s;
    }
}

// ---------------- capacity-constrained dispatch (k-major running count) ------------
__global__ void dispatch_kernel(float* __restrict__ disp, float* __restrict__ comb) {
    __shared__ int base[NE];
    __shared__ int whist[32][NE];
    __shared__ int wpref[32][NE];
    const int tid  = threadIdx.x;
    const int lane = tid & 31, warp = tid >> 5;
    if (tid < NE) base[tid] = 0;
    __syncthreads();

    for (int chunk = 0; chunk < 8; chunk++) {
        const int i = chunk * 1024 + tid;
        const int k = i >> 12;
        const int t = i & (N_TOK - 1);
        const int e   = (k == 0) ? g_e0[t] : g_e1[t];
        const float p = (k == 0) ? g_p0[t] : g_p1[t];

        if (lane < NE) whist[warp][lane] = 0;
        __syncwarp();
        const unsigned mm  = __match_any_sync(0xffffffffu, e);
        const unsigned blo = mm & ((1u << lane) - 1u);
        const int rank = __popc(blo);
        if (blo == 0u) whist[warp][e] = __popc(mm);
        __syncthreads();

        if (tid < NE) {
            int s = base[tid];
            for (int w = 0; w < 32; w++) { wpref[w][tid] = s; s += whist[w][tid]; }
            base[tid] = s;
        }
        __syncthreads();

        const int pos = wpref[warp][e] + rank;
        if (pos < CAP) {
            const size_t idx = ((size_t)t * NE + e) * CAP + pos;
            disp[idx] = 1.0f;
            comb[idx] = p;
        }
        __syncthreads();
    }
}

// ---------------- aux loss: deterministic tree reduce of 512 partials --------------
__global__ void aux_kernel(float* __restrict__ out_aux) {
    __shared__ float sm[512][16];
    const int tid = threadIdx.x;   // 512 threads
#pragma unroll
    for (int v = 0; v < 16; v++) sm[tid][v] = g_part[(size_t)tid * 16 + v];
    __syncthreads();
    for (int s = 256; s > 0; s >>= 1) {
        if (tid < s)
#pragma unroll
            for (int v = 0; v < 16; v++) sm[tid][v] += sm[tid + s][v];
        __syncthreads();
    }
    if (tid == 0) {
        float ent = 0.0f;
#pragma unroll
        for (int e = 0; e < NE; e++) {
            const float r = sm[0][e] / (float)N_TOK;
            ent += r * logf(r * 8.0f + 1e-9f);
        }
        float tot = 0.0f;
        float SI[NE];
#pragma unroll
        for (int e = 0; e < NE; e++) { SI[e] = sm[0][NE + e] + 1e-9f; tot += SI[e]; }
        float ie = 0.0f;
#pragma unroll
        for (int e = 0; e < NE; e++) {
            const float ip = SI[e] / tot;
            ie -= ip * logf(ip + 1e-9f);
        }
        out_aux[0] = ent - 0.1f * (ie / logf(8.0f));
    }
}

// ---------------- launch -----------------------------------------------------------
extern "C" void kernel_launch(void* const* d_in, const int* in_sizes, int n_in,
                              void* d_out, int out_size) {
    const float* x   = (const float*)d_in[0];
    const float* wi1 = (const float*)d_in[1];
    const float* bi1 = (const float*)d_in[2];
    const float* wi2 = (const float*)d_in[3];
    const float* bi2 = (const float*)d_in[4];
    const float* wr1 = (const float*)d_in[5];
    const float* br1 = (const float*)d_in[6];
    const float* wr2 = (const float*)d_in[7];
    const float* br2 = (const float*)d_in[8];
    const float* wu1 = (const float*)d_in[9];
    const float* bu1 = (const float*)d_in[10];
    const float* wu2 = (const float*)d_in[11];
    const float* bu2 = (const float*)d_in[12];

    float* out   = (float*)d_out;
    float* disp  = out;                                   // [4096, 8, 1536]
    float* comb  = disp + (size_t)N_TOK * NE * CAP;       // [4096, 8, 1536]
    float* probs = comb + (size_t)N_TOK * NE * CAP;       // [4096, 8]
    float* aux   = probs + (size_t)N_TOK * NE;            // [1]
    float* imp   = aux + 1;                               // [4096]

    cudaMemsetAsync(disp, 0, (size_t)2 * N_TOK * NE * CAP * sizeof(float), 0);

    gemmA_kernel<<<dim3(4, 32), 256>>>(x, wi1, bi1);
    importance_kernel<<<512, 256>>>(wi2, bi2, imp);
    compact_kernel<<<1, 1024>>>();
    gemmC_kernel<<<dim3(8, 34), 256>>>(x, wr1, br1, wu1, bu1);
    routing_kernel<<<512, 256>>>(wr2, br2, wu2, bu2, probs);
    dispatch_kernel<<<1, 1024>>>(disp, comb);
    aux_kernel<<<1, 512>>>(aux);
}